// round 5
// baseline (speedup 1.0000x reference)
#include <cuda_runtime.h>
#include <math.h>

// ---------------------------------------------------------------------------
// K[i,j] = | prod_k cos((x_ik - y_jk)/2) |
//        = | Px_i * Py_j * prod_k (1 + tan(x_ik/2)*tan(y_jk/2)) |
// Phase 1 (d==16): element-parallel sincos, warp-shuffle row cos-products.
// Phase 2: 64x64 tile, 256 thr, 4x4 f32x2 accs, t=fma(x,y,1); acc*=t.
// ---------------------------------------------------------------------------

#define MAXROWS 16384
#define MAXD 64

__device__ float g_Tx[MAXD * MAXROWS];
__device__ float g_Ty[MAXD * MAXROWS];
__device__ float g_Px[MAXROWS];
__device__ float g_Py[MAXROWS];

typedef unsigned long long ull;

__device__ __forceinline__ ull f2_mul(ull a, ull b) {
    ull r; asm("mul.rn.f32x2 %0, %1, %2;" : "=l"(r) : "l"(a), "l"(b)); return r;
}
__device__ __forceinline__ ull f2_fma(ull a, ull b, ull c) {
    ull r; asm("fma.rn.f32x2 %0, %1, %2, %3;" : "=l"(r) : "l"(a), "l"(b), "l"(c)); return r;
}
__device__ __forceinline__ ull f2_pack(float lo, float hi) {
    ull r;
    asm("mov.b64 %0, {%1, %2};" : "=l"(r) : "r"(__float_as_uint(lo)), "r"(__float_as_uint(hi)));
    return r;
}
__device__ __forceinline__ void f2_unpack(ull v, float& lo, float& hi) {
    unsigned int a, b;
    asm("mov.b64 {%0, %1}, %2;" : "=r"(a), "=r"(b) : "l"(v));
    lo = __uint_as_float(a); hi = __uint_as_float(b);
}

// --- Phase 1 (d==16): 16 lanes per row, shuffle product --------------------
__global__ void qk_pre16(const float* __restrict__ x,
                         const float* __restrict__ y, int n, int m) {
    int gwarp = (blockIdx.x * blockDim.x + threadIdx.x) >> 5;
    int lane = threadIdx.x & 31;
    int sub = lane >> 4;          // 2 rows per warp
    int k = lane & 15;
    int row = gwarp * 2 + sub;
    bool valid = row < n + m;
    float v = 0.0f;
    if (valid) v = (row < n) ? x[row * 16 + k] : y[(row - n) * 16 + k];
    float s, c;
    sincosf(0.5f * v, &s, &c);
    if (c == 0.0f) c = 1e-30f;
    float t = s / c;
    float p = c;
#pragma unroll
    for (int off = 8; off; off >>= 1)
        p *= __shfl_xor_sync(0xffffffffu, p, off);
    if (valid) {
        if (row < n) {
            g_Tx[k * n + row] = t;
            if (k == 0) g_Px[row] = p;
        } else {
            int j = row - n;
            g_Ty[k * m + j] = t;
            if (k == 0) g_Py[j] = p;
        }
    }
}

// --- Phase 1 generic (runtime d): one thread per row -----------------------
__global__ void qk_pre(const float* __restrict__ x, const float* __restrict__ y,
                       int n, int m, int d) {
    int i = blockIdx.x * blockDim.x + threadIdx.x;
    if (i >= n + m) return;
    const float* src = (i < n) ? x : y;
    int r = (i < n) ? i : i - n;
    int N = (i < n) ? n : m;
    float* tab = (i < n) ? g_Tx : g_Ty;
    float p = 1.0f;
    for (int k = 0; k < d; k++) {
        float s, c;
        sincosf(0.5f * src[r * d + k], &s, &c);
        if (c == 0.0f) c = 1e-30f;
        p *= c;
        tab[k * N + r] = s / c;
    }
    if (i < n) g_Px[r] = p; else g_Py[r] = p;
}

// --- Phase 2: 64x64 tile, 256 threads, 4 rows x 4 cols per thread ----------
template <int D>
__global__ __launch_bounds__(256, 4) void qk_tile(float* __restrict__ out,
                                                  int n, int m) {
    __shared__ __align__(16) float sTx[D][64];   // rows, planar
    __shared__ __align__(16) float sTy[D][64];   // cols, planar
    __shared__ __align__(16) float sPx[64];
    __shared__ __align__(16) float sPy[64];

    const int tid = threadIdx.x;
    const int bm0 = blockIdx.y * 64;
    const int bn0 = blockIdx.x * 64;

    for (int idx = tid; idx < D * 64; idx += 256) {
        int k = idx >> 6, r = idx & 63;
        int gi = bm0 + r; if (gi >= n) gi = n - 1;
        sTx[k][r] = g_Tx[k * n + gi];
        int gj = bn0 + r; if (gj >= m) gj = m - 1;
        sTy[k][r] = g_Ty[k * m + gj];
    }
    if (tid < 64) {
        int gi = bm0 + tid; if (gi >= n) gi = n - 1;
        sPx[tid] = g_Px[gi];
        int gj = bn0 + tid; if (gj >= m) gj = m - 1;
        sPy[tid] = g_Py[gj];
    }
    __syncthreads();

    const int tx = tid & 15;   // col group: cols j0..j0+3
    const int ty = tid >> 4;   // row group: rows i0..i0+3
    const int i0 = ty * 4;
    const int j0 = tx * 4;

    const ull ONE2 = f2_pack(1.0f, 1.0f);
    ull a00 = ONE2, a01 = ONE2, a10 = ONE2, a11 = ONE2;
    ull a20 = ONE2, a21 = ONE2, a30 = ONE2, a31 = ONE2;

#pragma unroll
    for (int k = 0; k < D; k++) {
        ulonglong2 yv = *reinterpret_cast<const ulonglong2*>(&sTy[k][j0]);
        float4 xv = *reinterpret_cast<const float4*>(&sTx[k][i0]);
        ull x0 = f2_pack(xv.x, xv.x);
        ull x1 = f2_pack(xv.y, xv.y);
        ull x2 = f2_pack(xv.z, xv.z);
        ull x3 = f2_pack(xv.w, xv.w);
        // t independent of acc -> acc chain is a single 4-cyc mul per k
        ull t00 = f2_fma(x0, yv.x, ONE2);
        ull t01 = f2_fma(x0, yv.y, ONE2);
        ull t10 = f2_fma(x1, yv.x, ONE2);
        ull t11 = f2_fma(x1, yv.y, ONE2);
        ull t20 = f2_fma(x2, yv.x, ONE2);
        ull t21 = f2_fma(x2, yv.y, ONE2);
        ull t30 = f2_fma(x3, yv.x, ONE2);
        ull t31 = f2_fma(x3, yv.y, ONE2);
        a00 = f2_mul(a00, t00);
        a01 = f2_mul(a01, t01);
        a10 = f2_mul(a10, t10);
        a11 = f2_mul(a11, t11);
        a20 = f2_mul(a20, t20);
        a21 = f2_mul(a21, t21);
        a30 = f2_mul(a30, t30);
        a31 = f2_mul(a31, t31);
    }

    // epilogue: scale by Px*Py, abs, store
    ulonglong2 pyv = *reinterpret_cast<const ulonglong2*>(&sPy[j0]);
    const bool interior = (bm0 + 63 < n) && (bn0 + 63 < m) && ((m & 3) == 0);

    ull r0[4] = {a00, a10, a20, a30};
    ull r1[4] = {a01, a11, a21, a31};
#pragma unroll
    for (int ii = 0; ii < 4; ii++) {
        float px = sPx[i0 + ii];
        ull pxp = f2_pack(px, px);
        ull v0 = f2_mul(f2_mul(r0[ii], pyv.x), pxp);
        ull v1 = f2_mul(f2_mul(r1[ii], pyv.y), pxp);
        float e0, e1, e2, e3;
        f2_unpack(v0, e0, e1);
        f2_unpack(v1, e2, e3);
        e0 = fabsf(e0); e1 = fabsf(e1); e2 = fabsf(e2); e3 = fabsf(e3);
        int gi = bm0 + i0 + ii;
        int gj = bn0 + j0;
        if (interior) {
            *reinterpret_cast<float4*>(&out[(long long)gi * m + gj]) =
                make_float4(e0, e1, e2, e3);
        } else if (gi < n) {
            if (gj + 0 < m) out[(long long)gi * m + gj + 0] = e0;
            if (gj + 1 < m) out[(long long)gi * m + gj + 1] = e1;
            if (gj + 2 < m) out[(long long)gi * m + gj + 2] = e2;
            if (gj + 3 < m) out[(long long)gi * m + gj + 3] = e3;
        }
    }
}

// --- generic fallback (runtime d) ------------------------------------------
__global__ void qk_generic(float* __restrict__ out, int n, int m, int d) {
    int j = blockIdx.x * blockDim.x + threadIdx.x;
    int i = blockIdx.y;
    if (j >= m || i >= n) return;
    float p = 1.0f;
    for (int k = 0; k < d; k++)
        p = fmaf(p * g_Tx[k * n + i], g_Ty[k * m + j], p);
    out[(long long)i * m + j] = fabsf(p * g_Px[i] * g_Py[j]);
}

extern "C" void kernel_launch(void* const* d_in, const int* in_sizes, int n_in,
                              void* d_out, int out_size) {
    const float* x = (const float*)d_in[0];
    const float* y = (const float*)d_in[1];
    float* out = (float*)d_out;

    long long s0 = in_sizes[0], s1 = in_sizes[1];
    int d = (int)(0.5 + sqrt((double)s0 * (double)s1 / (double)out_size));
    if (d < 1) d = 1;
    int n = (int)(s0 / d);
    int m = (int)(s1 / d);

    if (d == 16) {
        // 2 rows per warp, 16 rows per 256-thread block
        int rows = n + m;
        int blocks = (rows + 15) / 16;
        qk_pre16<<<blocks, 256>>>(x, y, n, m);
        dim3 grid((m + 63) / 64, (n + 63) / 64);
        qk_tile<16><<<grid, 256>>>(out, n, m);
    } else {
        int total = n + m;
        qk_pre<<<(total + 255) / 256, 256>>>(x, y, n, m, d);
        dim3 grid((m + 255) / 256, n);
        qk_generic<<<grid, 256>>>(out, n, m, d);
    }
}

// round 6
// speedup vs baseline: 1.3567x; 1.3567x over previous
#include <cuda_runtime.h>
#include <math.h>

// ---------------------------------------------------------------------------
// K[i,j] = | prod_k cos((x_ik - y_jk)/2) |
//        = | Px_i * Py_j * prod_k (1 + tan(x_ik/2)*tan(y_jk/2)) |
// Phase 1 (d==16): coalesced load, sincos, smem transpose, coalesced store.
// Phase 2: 64x64 tile; per k: t = tx*ty (2-operand mul), acc = fma(acc,t,acc)
//          (2 distinct operand pairs -> FFMA2 at rt 2, not 3).
// ---------------------------------------------------------------------------

#define MAXROWS 16384
#define MAXD 64

__device__ float g_Tx[MAXD * MAXROWS];
__device__ float g_Ty[MAXD * MAXROWS];
__device__ float g_Px[MAXROWS];
__device__ float g_Py[MAXROWS];

typedef unsigned long long ull;

__device__ __forceinline__ ull f2_mul(ull a, ull b) {
    ull r; asm("mul.rn.f32x2 %0, %1, %2;" : "=l"(r) : "l"(a), "l"(b)); return r;
}
__device__ __forceinline__ ull f2_fma(ull a, ull b, ull c) {
    ull r; asm("fma.rn.f32x2 %0, %1, %2, %3;" : "=l"(r) : "l"(a), "l"(b), "l"(c)); return r;
}
__device__ __forceinline__ ull f2_pack(float lo, float hi) {
    ull r;
    asm("mov.b64 %0, {%1, %2};" : "=l"(r) : "r"(__float_as_uint(lo)), "r"(__float_as_uint(hi)));
    return r;
}
__device__ __forceinline__ void f2_unpack(ull v, float& lo, float& hi) {
    unsigned int a, b;
    asm("mov.b64 {%0, %1}, %2;" : "=r"(a), "=r"(b) : "l"(v));
    lo = __uint_as_float(a); hi = __uint_as_float(b);
}

// --- Phase 1 (d==16): 512 thr/block, 32 rows/block, transposed coalesced out
__global__ __launch_bounds__(512) void qk_pre16(const float* __restrict__ x,
                                                const float* __restrict__ y,
                                                int n, int m) {
    __shared__ float sT[16][33];   // padded: conflict-free transpose
    __shared__ float sP[32];

    const int tid = threadIdx.x;
    const int r0 = blockIdx.x * 32;
    const int lane = tid & 31;
    const int k = lane & 15;
    const int rl = (tid >> 5) * 2 + (lane >> 4);  // local row 0..31
    const int row = r0 + rl;
    const bool valid = row < n + m;

    float v = 0.0f;
    if (valid) v = (row < n) ? x[row * 16 + k] : y[(row - n) * 16 + k];
    float s, c;
    sincosf(0.5f * v, &s, &c);
    if (c == 0.0f) c = 1e-30f;
    float t = s / c;
    float p = c;
#pragma unroll
    for (int off = 8; off; off >>= 1)        // product over the 16-lane half
        p *= __shfl_xor_sync(0xffffffffu, p, off);

    sT[k][rl] = t;
    if (k == 0) sP[rl] = p;
    __syncthreads();

    // coalesced store: warp w handles wire k=w, 32 consecutive rows
    const int ko = tid >> 5;       // 0..15
    const int ro = tid & 31;
    const int grow = r0 + ro;
    float tv = sT[ko][ro];
    if (grow < n) {
        g_Tx[ko * n + grow] = tv;
        if (ko == 0) g_Px[grow] = sP[ro];
    } else if (grow < n + m) {
        int j = grow - n;
        g_Ty[ko * m + j] = tv;
        if (ko == 0) g_Py[j] = sP[ro];
    }
}

// --- Phase 1 generic (runtime d) -------------------------------------------
__global__ void qk_pre(const float* __restrict__ x, const float* __restrict__ y,
                       int n, int m, int d) {
    int i = blockIdx.x * blockDim.x + threadIdx.x;
    if (i >= n + m) return;
    const float* src = (i < n) ? x : y;
    int r = (i < n) ? i : i - n;
    int N = (i < n) ? n : m;
    float* tab = (i < n) ? g_Tx : g_Ty;
    float p = 1.0f;
    for (int k = 0; k < d; k++) {
        float s, c;
        sincosf(0.5f * src[r * d + k], &s, &c);
        if (c == 0.0f) c = 1e-30f;
        p *= c;
        tab[k * N + r] = s / c;
    }
    if (i < n) g_Px[r] = p; else g_Py[r] = p;
}

// --- Phase 2: 64x64 tile, 256 threads, 4 rows x 4 cols per thread ----------
template <int D>
__global__ __launch_bounds__(256, 5) void qk_tile(float* __restrict__ out,
                                                  int n, int m) {
    // X duplicated ({v,v}): one LDS.128 = two ready broadcast f32x2 operands.
    __shared__ __align__(16) float sTx[D][128];
    __shared__ __align__(16) float sTy[D][64];
    __shared__ __align__(16) float sPx[64];
    __shared__ __align__(16) float sPy[64];

    const int tid = threadIdx.x;
    const int bm0 = blockIdx.y * 64;
    const int bn0 = blockIdx.x * 64;

    for (int idx = tid; idx < D * 64; idx += 256) {
        int k = idx >> 6, r = idx & 63;
        int gi = bm0 + r; if (gi >= n) gi = n - 1;
        float v = g_Tx[k * n + gi];
        *reinterpret_cast<float2*>(&sTx[k][2 * r]) = make_float2(v, v);
        int gj = bn0 + r; if (gj >= m) gj = m - 1;
        sTy[k][r] = g_Ty[k * m + gj];
    }
    if (tid < 64) {
        int gi = bm0 + tid; if (gi >= n) gi = n - 1;
        sPx[tid] = g_Px[gi];
        int gj = bn0 + tid; if (gj >= m) gj = m - 1;
        sPy[tid] = g_Py[gj];
    }
    __syncthreads();

    const int tx = tid & 15;
    const int ty = tid >> 4;
    const int i0 = ty * 4;
    const int j0 = tx * 4;

    const ull ONE2 = f2_pack(1.0f, 1.0f);
    ull a00 = ONE2, a01 = ONE2, a10 = ONE2, a11 = ONE2;
    ull a20 = ONE2, a21 = ONE2, a30 = ONE2, a31 = ONE2;

#pragma unroll
    for (int k = 0; k < D; k++) {
        ulonglong2 yv = *reinterpret_cast<const ulonglong2*>(&sTy[k][j0]);
        ulonglong2 xa = *reinterpret_cast<const ulonglong2*>(&sTx[k][2 * i0]);
        ulonglong2 xb = *reinterpret_cast<const ulonglong2*>(&sTx[k][2 * i0 + 4]);
        // t = tx*ty (acc-independent), then acc = acc*t + acc.
        // fma(acc, t, acc): 2 distinct operand pairs -> rt 2 on the fma pipe.
        ull t00 = f2_mul(xa.x, yv.x);
        ull t01 = f2_mul(xa.x, yv.y);
        ull t10 = f2_mul(xa.y, yv.x);
        ull t11 = f2_mul(xa.y, yv.y);
        ull t20 = f2_mul(xb.x, yv.x);
        ull t21 = f2_mul(xb.x, yv.y);
        ull t30 = f2_mul(xb.y, yv.x);
        ull t31 = f2_mul(xb.y, yv.y);
        a00 = f2_fma(a00, t00, a00);
        a01 = f2_fma(a01, t01, a01);
        a10 = f2_fma(a10, t10, a10);
        a11 = f2_fma(a11, t11, a11);
        a20 = f2_fma(a20, t20, a20);
        a21 = f2_fma(a21, t21, a21);
        a30 = f2_fma(a30, t30, a30);
        a31 = f2_fma(a31, t31, a31);
    }

    ulonglong2 pyv = *reinterpret_cast<const ulonglong2*>(&sPy[j0]);
    const bool interior = (bm0 + 63 < n) && (bn0 + 63 < m) && ((m & 3) == 0);

    ull r0[4] = {a00, a10, a20, a30};
    ull r1[4] = {a01, a11, a21, a31};
#pragma unroll
    for (int ii = 0; ii < 4; ii++) {
        float px = sPx[i0 + ii];
        ull pxp = f2_pack(px, px);
        ull v0 = f2_mul(f2_mul(r0[ii], pyv.x), pxp);
        ull v1 = f2_mul(f2_mul(r1[ii], pyv.y), pxp);
        float e0, e1, e2, e3;
        f2_unpack(v0, e0, e1);
        f2_unpack(v1, e2, e3);
        e0 = fabsf(e0); e1 = fabsf(e1); e2 = fabsf(e2); e3 = fabsf(e3);
        int gi = bm0 + i0 + ii;
        int gj = bn0 + j0;
        if (interior) {
            *reinterpret_cast<float4*>(&out[(long long)gi * m + gj]) =
                make_float4(e0, e1, e2, e3);
        } else if (gi < n) {
            if (gj + 0 < m) out[(long long)gi * m + gj + 0] = e0;
            if (gj + 1 < m) out[(long long)gi * m + gj + 1] = e1;
            if (gj + 2 < m) out[(long long)gi * m + gj + 2] = e2;
            if (gj + 3 < m) out[(long long)gi * m + gj + 3] = e3;
        }
    }
}

// --- generic fallback (runtime d) ------------------------------------------
__global__ void qk_generic(float* __restrict__ out, int n, int m, int d) {
    int j = blockIdx.x * blockDim.x + threadIdx.x;
    int i = blockIdx.y;
    if (j >= m || i >= n) return;
    float p = 1.0f;
    for (int k = 0; k < d; k++)
        p = fmaf(p * g_Tx[k * n + i], g_Ty[k * m + j], p);
    out[(long long)i * m + j] = fabsf(p * g_Px[i] * g_Py[j]);
}

extern "C" void kernel_launch(void* const* d_in, const int* in_sizes, int n_in,
                              void* d_out, int out_size) {
    const float* x = (const float*)d_in[0];
    const float* y = (const float*)d_in[1];
    float* out = (float*)d_out;

    long long s0 = in_sizes[0], s1 = in_sizes[1];
    int d = (int)(0.5 + sqrt((double)s0 * (double)s1 / (double)out_size));
    if (d < 1) d = 1;
    int n = (int)(s0 / d);
    int m = (int)(s1 / d);

    if (d == 16) {
        int rows = n + m;
        qk_pre16<<<(rows + 31) / 32, 512>>>(x, y, n, m);
        dim3 grid((m + 63) / 64, (n + 63) / 64);
        qk_tile<16><<<grid, 256>>>(out, n, m);
    } else {
        int total = n + m;
        qk_pre<<<(total + 255) / 256, 256>>>(x, y, n, m, d);
        dim3 grid((m + 255) / 256, n);
        qk_generic<<<grid, 256>>>(out, n, m, d);
    }
}

// round 7
// speedup vs baseline: 1.6055x; 1.1834x over previous
#include <cuda_runtime.h>
#include <math.h>

// ---------------------------------------------------------------------------
// K[i,j] = | prod_k cos((x_ik - y_jk)/2) |
//        = | Px_i * Py_j * prod_k (1 + tan(x_ik/2)*tan(y_jk/2)) |
// d==16: SINGLE fused kernel. Each CTA computes tan/cos-products for its own
// 64 rows + 64 cols in the prologue (fast-math MUFU work, overlapped with
// other CTAs' FMA mainloops), then runs the proven 64x64 f32x2 product loop.
// ---------------------------------------------------------------------------

#define MAXROWS 16384
#define MAXD 64

// scratch for the generic (d != 16) fallback path only
__device__ float g_Tx[MAXD * MAXROWS];
__device__ float g_Ty[MAXD * MAXROWS];
__device__ float g_Px[MAXROWS];
__device__ float g_Py[MAXROWS];

typedef unsigned long long ull;

__device__ __forceinline__ ull f2_mul(ull a, ull b) {
    ull r; asm("mul.rn.f32x2 %0, %1, %2;" : "=l"(r) : "l"(a), "l"(b)); return r;
}
__device__ __forceinline__ ull f2_fma(ull a, ull b, ull c) {
    ull r; asm("fma.rn.f32x2 %0, %1, %2, %3;" : "=l"(r) : "l"(a), "l"(b), "l"(c)); return r;
}
__device__ __forceinline__ ull f2_pack(float lo, float hi) {
    ull r;
    asm("mov.b64 %0, {%1, %2};" : "=l"(r) : "r"(__float_as_uint(lo)), "r"(__float_as_uint(hi)));
    return r;
}
__device__ __forceinline__ void f2_unpack(ull v, float& lo, float& hi) {
    unsigned int a, b;
    asm("mov.b64 {%0, %1}, %2;" : "=r"(a), "=r"(b) : "l"(v));
    lo = __uint_as_float(a); hi = __uint_as_float(b);
}

// --- fused d==16 kernel: 64x64 tile, 256 threads, 4x4 f32x2 per thread -----
__global__ __launch_bounds__(256, 5) void qk_fused16(float* __restrict__ out,
                                                     const float* __restrict__ x,
                                                     const float* __restrict__ y,
                                                     int n, int m) {
    __shared__ __align__(16) float sTx[16][128];  // rows, duplicated {v,v}
    __shared__ __align__(16) float sTy[16][64];   // cols, planar
    __shared__ __align__(16) float sPx[64];
    __shared__ __align__(16) float sPy[64];

    const int tid = threadIdx.x;
    const int bm0 = blockIdx.y * 64;
    const int bn0 = blockIdx.x * 64;

    // ---- prologue: compute tans + row cos-products in-CTA (MUFU work) ----
    // threads 0..127: x side (thread = half-row), 128..255: y side.
    {
        const int half = tid & 1;          // which 8 wires
        float p = 1.0f;
        if (tid < 128) {
            const int r = tid >> 1;        // local row 0..63
            int gi = bm0 + r; if (gi >= n) gi = n - 1;
            const float4* src = reinterpret_cast<const float4*>(x + gi * 16 + half * 8);
            float4 va = src[0], vb = src[1];
            float vals[8] = {va.x, va.y, va.z, va.w, vb.x, vb.y, vb.z, vb.w};
#pragma unroll
            for (int w = 0; w < 8; w++) {
                float s, c;
                __sincosf(0.5f * vals[w], &s, &c);
                if (c == 0.0f) c = 1e-30f;
                p *= c;
                float t = __fdividef(s, c);
                *reinterpret_cast<float2*>(&sTx[half * 8 + w][2 * r]) = make_float2(t, t);
            }
            p *= __shfl_xor_sync(0xffffffffu, p, 1);
            if (half == 0) sPx[r] = p;
        } else {
            const int r = (tid - 128) >> 1;
            int gj = bn0 + r; if (gj >= m) gj = m - 1;
            const float4* src = reinterpret_cast<const float4*>(y + gj * 16 + half * 8);
            float4 va = src[0], vb = src[1];
            float vals[8] = {va.x, va.y, va.z, va.w, vb.x, vb.y, vb.z, vb.w};
#pragma unroll
            for (int w = 0; w < 8; w++) {
                float s, c;
                __sincosf(0.5f * vals[w], &s, &c);
                if (c == 0.0f) c = 1e-30f;
                p *= c;
                sTy[half * 8 + w][r] = __fdividef(s, c);
            }
            p *= __shfl_xor_sync(0xffffffffu, p, 1);
            if (half == 0) sPy[r] = p;
        }
    }
    __syncthreads();

    // ---- main loop (proven core) ----
    const int tx = tid & 15;
    const int ty = tid >> 4;
    const int i0 = ty * 4;
    const int j0 = tx * 4;

    const ull ONE2 = f2_pack(1.0f, 1.0f);
    ull a00 = ONE2, a01 = ONE2, a10 = ONE2, a11 = ONE2;
    ull a20 = ONE2, a21 = ONE2, a30 = ONE2, a31 = ONE2;

#pragma unroll
    for (int k = 0; k < 16; k++) {
        ulonglong2 yv = *reinterpret_cast<const ulonglong2*>(&sTy[k][j0]);
        ulonglong2 xa = *reinterpret_cast<const ulonglong2*>(&sTx[k][2 * i0]);
        ulonglong2 xb = *reinterpret_cast<const ulonglong2*>(&sTx[k][2 * i0 + 4]);
        ull t00 = f2_mul(xa.x, yv.x);
        ull t01 = f2_mul(xa.x, yv.y);
        ull t10 = f2_mul(xa.y, yv.x);
        ull t11 = f2_mul(xa.y, yv.y);
        ull t20 = f2_mul(xb.x, yv.x);
        ull t21 = f2_mul(xb.x, yv.y);
        ull t30 = f2_mul(xb.y, yv.x);
        ull t31 = f2_mul(xb.y, yv.y);
        a00 = f2_fma(a00, t00, a00);
        a01 = f2_fma(a01, t01, a01);
        a10 = f2_fma(a10, t10, a10);
        a11 = f2_fma(a11, t11, a11);
        a20 = f2_fma(a20, t20, a20);
        a21 = f2_fma(a21, t21, a21);
        a30 = f2_fma(a30, t30, a30);
        a31 = f2_fma(a31, t31, a31);
    }

    ulonglong2 pyv = *reinterpret_cast<const ulonglong2*>(&sPy[j0]);
    const bool interior = (bm0 + 63 < n) && (bn0 + 63 < m) && ((m & 3) == 0);

    ull r0[4] = {a00, a10, a20, a30};
    ull r1[4] = {a01, a11, a21, a31};
#pragma unroll
    for (int ii = 0; ii < 4; ii++) {
        float px = sPx[i0 + ii];
        ull pxp = f2_pack(px, px);
        ull v0 = f2_mul(f2_mul(r0[ii], pyv.x), pxp);
        ull v1 = f2_mul(f2_mul(r1[ii], pyv.y), pxp);
        float e0, e1, e2, e3;
        f2_unpack(v0, e0, e1);
        f2_unpack(v1, e2, e3);
        e0 = fabsf(e0); e1 = fabsf(e1); e2 = fabsf(e2); e3 = fabsf(e3);
        int gi = bm0 + i0 + ii;
        int gj = bn0 + j0;
        if (interior) {
            *reinterpret_cast<float4*>(&out[(long long)gi * m + gj]) =
                make_float4(e0, e1, e2, e3);
        } else if (gi < n) {
            if (gj + 0 < m) out[(long long)gi * m + gj + 0] = e0;
            if (gj + 1 < m) out[(long long)gi * m + gj + 1] = e1;
            if (gj + 2 < m) out[(long long)gi * m + gj + 2] = e2;
            if (gj + 3 < m) out[(long long)gi * m + gj + 3] = e3;
        }
    }
}

// --- generic fallback path (runtime d): two kernels ------------------------
__global__ void qk_pre(const float* __restrict__ x, const float* __restrict__ y,
                       int n, int m, int d) {
    int i = blockIdx.x * blockDim.x + threadIdx.x;
    if (i >= n + m) return;
    const float* src = (i < n) ? x : y;
    int r = (i < n) ? i : i - n;
    int N = (i < n) ? n : m;
    float* tab = (i < n) ? g_Tx : g_Ty;
    float p = 1.0f;
    for (int k = 0; k < d; k++) {
        float s, c;
        sincosf(0.5f * src[r * d + k], &s, &c);
        if (c == 0.0f) c = 1e-30f;
        p *= c;
        tab[k * N + r] = s / c;
    }
    if (i < n) g_Px[r] = p; else g_Py[r] = p;
}

__global__ void qk_generic(float* __restrict__ out, int n, int m, int d) {
    int j = blockIdx.x * blockDim.x + threadIdx.x;
    int i = blockIdx.y;
    if (j >= m || i >= n) return;
    float p = 1.0f;
    for (int k = 0; k < d; k++)
        p = fmaf(p * g_Tx[k * n + i], g_Ty[k * m + j], p);
    out[(long long)i * m + j] = fabsf(p * g_Px[i] * g_Py[j]);
}

extern "C" void kernel_launch(void* const* d_in, const int* in_sizes, int n_in,
                              void* d_out, int out_size) {
    const float* x = (const float*)d_in[0];
    const float* y = (const float*)d_in[1];
    float* out = (float*)d_out;

    long long s0 = in_sizes[0], s1 = in_sizes[1];
    int d = (int)(0.5 + sqrt((double)s0 * (double)s1 / (double)out_size));
    if (d < 1) d = 1;
    int n = (int)(s0 / d);
    int m = (int)(s1 / d);

    if (d == 16) {
        dim3 grid((m + 63) / 64, (n + 63) / 64);
        qk_fused16<<<grid, 256>>>(out, x, y, n, m);
    } else {
        int total = n + m;
        qk_pre<<<(total + 255) / 256, 256>>>(x, y, n, m, d);
        dim3 grid((m + 255) / 256, n);
        qk_generic<<<grid, 256>>>(out, n, m, d);
    }
}

// round 8
// speedup vs baseline: 1.6469x; 1.0258x over previous
#include <cuda_runtime.h>
#include <math.h>

// ---------------------------------------------------------------------------
// K[i,j] = | prod_k cos((x_ik - y_jk)/2) |
//        = | Px_i * Py_j * prod_k (1 + tan(x_ik/2)*tan(y_jk/2)) |
// d==16: single fused kernel; per-CTA tan/cos-product prologue (MUFU,
// overlapped), 64x64 tile, 4x4 f32x2 per thread, occ-6 (<=42 regs).
// ---------------------------------------------------------------------------

#define MAXROWS 16384
#define MAXD 64

// scratch for the generic (d != 16) fallback path only
__device__ float g_Tx[MAXD * MAXROWS];
__device__ float g_Ty[MAXD * MAXROWS];
__device__ float g_Px[MAXROWS];
__device__ float g_Py[MAXROWS];

typedef unsigned long long ull;

__device__ __forceinline__ ull f2_mul(ull a, ull b) {
    ull r; asm("mul.rn.f32x2 %0, %1, %2;" : "=l"(r) : "l"(a), "l"(b)); return r;
}
__device__ __forceinline__ ull f2_fma(ull a, ull b, ull c) {
    ull r; asm("fma.rn.f32x2 %0, %1, %2, %3;" : "=l"(r) : "l"(a), "l"(b), "l"(c)); return r;
}
__device__ __forceinline__ ull f2_pack(float lo, float hi) {
    ull r;
    asm("mov.b64 %0, {%1, %2};" : "=l"(r) : "r"(__float_as_uint(lo)), "r"(__float_as_uint(hi)));
    return r;
}
__device__ __forceinline__ void f2_unpack(ull v, float& lo, float& hi) {
    unsigned int a, b;
    asm("mov.b64 {%0, %1}, %2;" : "=r"(a), "=r"(b) : "l"(v));
    lo = __uint_as_float(a); hi = __uint_as_float(b);
}

// --- fused d==16 kernel ----------------------------------------------------
__global__ __launch_bounds__(256, 6) void qk_fused16(float* __restrict__ out,
                                                     const float* __restrict__ x,
                                                     const float* __restrict__ y,
                                                     int n, int m) {
    __shared__ __align__(16) float sTx[16][128];  // rows, duplicated {v,v}
    __shared__ __align__(16) float sTy[16][64];   // cols, planar
    __shared__ __align__(16) float sPx[64];
    __shared__ __align__(16) float sPy[64];

    const int tid = threadIdx.x;
    const int bm0 = blockIdx.y * 64;
    const int bn0 = blockIdx.x * 64;

    // ---- prologue: per-CTA tans + row cos-products (MUFU work) ----
    {
        const int half = tid & 1;          // which 8 wires
        float p = 1.0f;
        if (tid < 128) {
            const int r = tid >> 1;        // local row 0..63
            int gi = bm0 + r; if (gi >= n) gi = n - 1;
            const float4* src = reinterpret_cast<const float4*>(x + gi * 16 + half * 8);
            float4 va = src[0], vb = src[1];
            float vals[8] = {va.x, va.y, va.z, va.w, vb.x, vb.y, vb.z, vb.w};
#pragma unroll
            for (int w = 0; w < 8; w++) {
                float s, c;
                __sincosf(0.5f * vals[w], &s, &c);
                c = (c == 0.0f) ? 1e-30f : c;
                p *= c;
                float t = __fdividef(s, c);
                *reinterpret_cast<float2*>(&sTx[half * 8 + w][2 * r]) = make_float2(t, t);
            }
            p *= __shfl_xor_sync(0xffffffffu, p, 1);
            if (half == 0) sPx[r] = p;
        } else {
            const int r = (tid - 128) >> 1;
            int gj = bn0 + r; if (gj >= m) gj = m - 1;
            const float4* src = reinterpret_cast<const float4*>(y + gj * 16 + half * 8);
            float4 va = src[0], vb = src[1];
            float vals[8] = {va.x, va.y, va.z, va.w, vb.x, vb.y, vb.z, vb.w};
#pragma unroll
            for (int w = 0; w < 8; w++) {
                float s, c;
                __sincosf(0.5f * vals[w], &s, &c);
                c = (c == 0.0f) ? 1e-30f : c;
                p *= c;
                sTy[half * 8 + w][r] = __fdividef(s, c);
            }
            p *= __shfl_xor_sync(0xffffffffu, p, 1);
            if (half == 0) sPy[r] = p;
        }
    }
    __syncthreads();

    // ---- main loop ----
    const int tx = tid & 15;
    const int ty = tid >> 4;
    const int i0 = ty * 4;
    const int j0 = tx * 4;

    const ull ONE2 = f2_pack(1.0f, 1.0f);
    ull a00 = ONE2, a01 = ONE2, a10 = ONE2, a11 = ONE2;
    ull a20 = ONE2, a21 = ONE2, a30 = ONE2, a31 = ONE2;

#pragma unroll
    for (int k = 0; k < 16; k++) {
        ulonglong2 yv = *reinterpret_cast<const ulonglong2*>(&sTy[k][j0]);
        ulonglong2 xa = *reinterpret_cast<const ulonglong2*>(&sTx[k][2 * i0]);
        ulonglong2 xb = *reinterpret_cast<const ulonglong2*>(&sTx[k][2 * i0 + 4]);
        ull t00 = f2_mul(xa.x, yv.x);
        ull t01 = f2_mul(xa.x, yv.y);
        ull t10 = f2_mul(xa.y, yv.x);
        ull t11 = f2_mul(xa.y, yv.y);
        ull t20 = f2_mul(xb.x, yv.x);
        ull t21 = f2_mul(xb.x, yv.y);
        ull t30 = f2_mul(xb.y, yv.x);
        ull t31 = f2_mul(xb.y, yv.y);
        a00 = f2_fma(a00, t00, a00);
        a01 = f2_fma(a01, t01, a01);
        a10 = f2_fma(a10, t10, a10);
        a11 = f2_fma(a11, t11, a11);
        a20 = f2_fma(a20, t20, a20);
        a21 = f2_fma(a21, t21, a21);
        a30 = f2_fma(a30, t30, a30);
        a31 = f2_fma(a31, t31, a31);
    }

    // ---- epilogue: scale, abs, store (no arrays -> low reg pressure) ----
    ulonglong2 pyv = *reinterpret_cast<const ulonglong2*>(&sPy[j0]);
    const bool interior = (bm0 + 63 < n) && (bn0 + 63 < m) && ((m & 3) == 0);
    const int gj = bn0 + j0;

#define QK_EMIT(II, A0, A1)                                                   \
    {                                                                         \
        float px = sPx[i0 + (II)];                                            \
        ull pxp = f2_pack(px, px);                                            \
        ull v0 = f2_mul(f2_mul((A0), pyv.x), pxp);                            \
        ull v1 = f2_mul(f2_mul((A1), pyv.y), pxp);                            \
        float e0, e1, e2, e3;                                                 \
        f2_unpack(v0, e0, e1);                                                \
        f2_unpack(v1, e2, e3);                                                \
        e0 = fabsf(e0); e1 = fabsf(e1); e2 = fabsf(e2); e3 = fabsf(e3);       \
        int gi = bm0 + i0 + (II);                                             \
        if (interior) {                                                       \
            *reinterpret_cast<float4*>(&out[(long long)gi * m + gj]) =        \
                make_float4(e0, e1, e2, e3);                                  \
        } else if (gi < n) {                                                  \
            if (gj + 0 < m) out[(long long)gi * m + gj + 0] = e0;             \
            if (gj + 1 < m) out[(long long)gi * m + gj + 1] = e1;             \
            if (gj + 2 < m) out[(long long)gi * m + gj + 2] = e2;             \
            if (gj + 3 < m) out[(long long)gi * m + gj + 3] = e3;             \
        }                                                                     \
    }

    QK_EMIT(0, a00, a01)
    QK_EMIT(1, a10, a11)
    QK_EMIT(2, a20, a21)
    QK_EMIT(3, a30, a31)
#undef QK_EMIT
}

// --- generic fallback path (runtime d): two kernels ------------------------
__global__ void qk_pre(const float* __restrict__ x, const float* __restrict__ y,
                       int n, int m, int d) {
    int i = blockIdx.x * blockDim.x + threadIdx.x;
    if (i >= n + m) return;
    const float* src = (i < n) ? x : y;
    int r = (i < n) ? i : i - n;
    int N = (i < n) ? n : m;
    float* tab = (i < n) ? g_Tx : g_Ty;
    float p = 1.0f;
    for (int k = 0; k < d; k++) {
        float s, c;
        sincosf(0.5f * src[r * d + k], &s, &c);
        if (c == 0.0f) c = 1e-30f;
        p *= c;
        tab[k * N + r] = s / c;
    }
    if (i < n) g_Px[r] = p; else g_Py[r] = p;
}

__global__ void qk_generic(float* __restrict__ out, int n, int m, int d) {
    int j = blockIdx.x * blockDim.x + threadIdx.x;
    int i = blockIdx.y;
    if (j >= m || i >= n) return;
    float p = 1.0f;
    for (int k = 0; k < d; k++)
        p = fmaf(p * g_Tx[k * n + i], g_Ty[k * m + j], p);
    out[(long long)i * m + j] = fabsf(p * g_Px[i] * g_Py[j]);
}

extern "C" void kernel_launch(void* const* d_in, const int* in_sizes, int n_in,
                              void* d_out, int out_size) {
    const float* x = (const float*)d_in[0];
    const float* y = (const float*)d_in[1];
    float* out = (float*)d_out;

    long long s0 = in_sizes[0], s1 = in_sizes[1];
    int d = (int)(0.5 + sqrt((double)s0 * (double)s1 / (double)out_size));
    if (d < 1) d = 1;
    int n = (int)(s0 / d);
    int m = (int)(s1 / d);

    if (d == 16) {
        dim3 grid((m + 63) / 64, (n + 63) / 64);
        qk_fused16<<<grid, 256>>>(out, x, y, n, m);
    } else {
        int total = n + m;
        qk_pre<<<(total + 255) / 256, 256>>>(x, y, n, m, d);
        dim3 grid((m + 255) / 256, n);
        qk_generic<<<grid, 256>>>(out, n, m, d);
    }
}